// round 3
// baseline (speedup 1.0000x reference)
#include <cuda_runtime.h>
#include <cstdint>

#define N_NODES 100000
#define N_EDGES 3200000
#define DIM 64

// Scratch (device globals: no allocation allowed).
__device__ float4 g_hbuf[2][(size_t)N_NODES * 16];
__device__ int    g_off[N_NODES + 1];
__device__ int    g_cur[N_NODES];
__device__ int2   g_edge[N_EDGES];          // (src, float_bits(a)) permuted by dst

// ---------------- CSR build ----------------

__global__ void zero_int_kernel(int* __restrict__ p, int n) {
    int i = blockIdx.x * blockDim.x + threadIdx.x;
    if (i < n) p[i] = 0;
}

__global__ void hist_kernel(const int* __restrict__ dst, int* __restrict__ cnt, int ne) {
    int e0 = (blockIdx.x * blockDim.x + threadIdx.x) * 4;
    if (e0 + 4 <= ne) {
        int4 d = *(const int4*)(dst + e0);
        atomicAdd(&cnt[d.x], 1);
        atomicAdd(&cnt[d.y], 1);
        atomicAdd(&cnt[d.z], 1);
        atomicAdd(&cnt[d.w], 1);
    } else {
        for (int e = e0; e < ne; e++) atomicAdd(&cnt[__ldg(dst + e)], 1);
    }
}

// Single-block exclusive scan over cnt[0..n) -> off[0..n]; also cur[v] = off[v].
__global__ void scan_kernel(int* __restrict__ cnt, int* __restrict__ off,
                            int* __restrict__ cur, int n) {
    __shared__ int sh[1024];
    int t = threadIdx.x;
    int C = (n + 1023) >> 10;
    int base = t * C;
    int sum = 0;
    for (int i = 0; i < C; i++) {
        int idx = base + i;
        if (idx < n) sum += cnt[idx];
    }
    sh[t] = sum;
    __syncthreads();
    for (int d = 1; d < 1024; d <<= 1) {
        int tmp = (t >= d) ? sh[t - d] : 0;
        __syncthreads();
        sh[t] += tmp;
        __syncthreads();
    }
    int run = sh[t] - sum;
    for (int i = 0; i < C; i++) {
        int idx = base + i;
        if (idx < n) {
            int c = cnt[idx];
            off[idx] = run;
            cur[idx] = run;
            run += c;
        }
    }
    if (t == 1023) off[n] = sh[1023];
}

__global__ void scatter_kernel(const int* __restrict__ src, const int* __restrict__ dst,
                               const float* __restrict__ a,
                               int* __restrict__ cur, int2* __restrict__ edge, int ne) {
    int e0 = (blockIdx.x * blockDim.x + threadIdx.x) * 4;
    if (e0 + 4 <= ne) {
        int4   d4 = *(const int4*)(dst + e0);
        int4   s4 = *(const int4*)(src + e0);
        float4 a4 = *(const float4*)(a + e0);
        int p0 = atomicAdd(&cur[d4.x], 1);
        int p1 = atomicAdd(&cur[d4.y], 1);
        int p2 = atomicAdd(&cur[d4.z], 1);
        int p3 = atomicAdd(&cur[d4.w], 1);
        edge[p0] = make_int2(s4.x, __float_as_int(a4.x));
        edge[p1] = make_int2(s4.y, __float_as_int(a4.y));
        edge[p2] = make_int2(s4.z, __float_as_int(a4.z));
        edge[p3] = make_int2(s4.w, __float_as_int(a4.w));
    } else {
        for (int e = e0; e < ne; e++) {
            int d = __ldg(dst + e);
            int pos = atomicAdd(&cur[d], 1);
            edge[pos] = make_int2(__ldg(src + e), __float_as_int(__ldg(a + e)));
        }
    }
}

// ---------------- Fused layer: aggregate + dual-GEMM + activation ----------------
// Block = 128 nodes, 256 threads.
// Phase 1: 16 groups x 16 threads aggregate h_n for 8 nodes each; write S/P tiles.
// Phase 2: 4-node x 8-dim register tile per thread, packed fma.rn.f32x2.

#define PAD 68   // 272B row stride: 16B-aligned, 2-way-max bank pattern

__device__ __forceinline__ void fma2(unsigned long long& acc,
                                     unsigned long long ab, unsigned long long bb) {
    asm("fma.rn.f32x2 %0, %1, %2, %0;" : "+l"(acc) : "l"(ab), "l"(bb));
}
__device__ __forceinline__ unsigned long long dup2(float s) {
    unsigned long long r;
    unsigned int u = __float_as_uint(s);
    asm("mov.b64 %0, {%1, %1};" : "=l"(r) : "r"(u));
    return r;
}
__device__ __forceinline__ float2 unpk(unsigned long long v) {
    unsigned int lo, hi;
    asm("mov.b64 {%0, %1}, %2;" : "=r"(lo), "=r"(hi) : "l"(v));
    return make_float2(__uint_as_float(lo), __uint_as_float(hi));
}

__global__ void __launch_bounds__(256, 2)
layer_kernel(const float4* __restrict__ hin,
             const int*  __restrict__ off,
             const int2* __restrict__ edge,
             const float4* __restrict__ W1, const float* __restrict__ b1,
             const float4* __restrict__ W2, const float* __restrict__ b2,
             float4* __restrict__ hout, float* __restrict__ out,
             int out_off, int n, int write_x) {
    extern __shared__ float sm[];
    float* Ssh  = sm;                  // [128][PAD]
    float* Psh  = Ssh + 128 * PAD;     // [128][PAD]
    float* W1sh = Psh + 128 * PAD;     // [64][64] [k][j]
    float* W2sh = W1sh + 4096;
    float* b1sh = W2sh + 4096;
    float* b2sh = b1sh + 64;

    int tid = threadIdx.x;
    int node0 = blockIdx.x << 7;

    for (int i = tid; i < 1024; i += 256) {
        ((float4*)W1sh)[i] = __ldg(W1 + i);
        ((float4*)W2sh)[i] = __ldg(W2 + i);
    }
    if (tid < 64) { b1sh[tid] = __ldg(b1 + tid); b2sh[tid] = __ldg(b2 + tid); }

    // ---- Phase 1: aggregation ----
    int grp = tid >> 4, c = tid & 15;
    for (int q = 0; q < 8; q++) {
        int nl = (grp << 3) + q;
        int v = node0 + nl;
        float4 hv   = make_float4(0.f, 0.f, 0.f, 0.f);
        float4 acca = make_float4(0.f, 0.f, 0.f, 0.f);
        float4 accb = make_float4(0.f, 0.f, 0.f, 0.f);
        if (v < n) {
            hv = __ldg(hin + ((size_t)v << 4) + c);
            int i = __ldg(off + v), end = __ldg(off + v + 1);
            for (; i + 2 <= end; i += 2) {
                int2 ea = __ldg(edge + i);
                int2 eb = __ldg(edge + i + 1);
                float4 ha = __ldg(hin + ((size_t)ea.x << 4) + c);
                float4 hb = __ldg(hin + ((size_t)eb.x << 4) + c);
                float wa = __int_as_float(ea.y), wb = __int_as_float(eb.y);
                acca.x += wa * ha.x; acca.y += wa * ha.y;
                acca.z += wa * ha.z; acca.w += wa * ha.w;
                accb.x += wb * hb.x; accb.y += wb * hb.y;
                accb.z += wb * hb.z; accb.w += wb * hb.w;
            }
            if (i < end) {
                int2 ea = __ldg(edge + i);
                float4 ha = __ldg(hin + ((size_t)ea.x << 4) + c);
                float wa = __int_as_float(ea.y);
                acca.x += wa * ha.x; acca.y += wa * ha.y;
                acca.z += wa * ha.z; acca.w += wa * ha.w;
            }
            if (write_x) *(float4*)(out + (size_t)v * 256 + (c << 2)) = hv;
        }
        float4 hn4 = make_float4(acca.x + accb.x, acca.y + accb.y,
                                 acca.z + accb.z, acca.w + accb.w);
        float4 s4 = make_float4(hv.x + hn4.x, hv.y + hn4.y, hv.z + hn4.z, hv.w + hn4.w);
        float4 p4 = make_float4(hv.x * hn4.x, hv.y * hn4.y, hv.z * hn4.z, hv.w * hn4.w);
        *(float4*)(Ssh + nl * PAD + (c << 2)) = s4;
        *(float4*)(Psh + nl * PAD + (c << 2)) = p4;
    }
    __syncthreads();

    // ---- Phase 2: dual GEMM, packed f32x2 ----
    int tx = tid & 7;            // j0 = tx*8
    int ty = tid >> 3;           // nodes ty*4 .. ty*4+3
    unsigned long long a1[4][4] = {};
    unsigned long long a2[4][4] = {};

#pragma unroll 4
    for (int k = 0; k < 64; k++) {
        const float* w1p = W1sh + (k << 6) + (tx << 3);
        const float* w2p = W2sh + (k << 6) + (tx << 3);
        ulonglong2 w1lo = *(const ulonglong2*)(w1p);
        ulonglong2 w1hi = *(const ulonglong2*)(w1p + 4);
        ulonglong2 w2lo = *(const ulonglong2*)(w2p);
        ulonglong2 w2hi = *(const ulonglong2*)(w2p + 4);
#pragma unroll
        for (int i = 0; i < 4; i++) {
            float s = Ssh[(ty * 4 + i) * PAD + k];
            float p = Psh[(ty * 4 + i) * PAD + k];
            unsigned long long ss = dup2(s), pp = dup2(p);
            fma2(a1[i][0], ss, w1lo.x);
            fma2(a1[i][1], ss, w1lo.y);
            fma2(a1[i][2], ss, w1hi.x);
            fma2(a1[i][3], ss, w1hi.y);
            fma2(a2[i][0], pp, w2lo.x);
            fma2(a2[i][1], pp, w2lo.y);
            fma2(a2[i][2], pp, w2hi.x);
            fma2(a2[i][3], pp, w2hi.y);
        }
    }

    int j0 = tx << 3;
#pragma unroll
    for (int i = 0; i < 4; i++) {
        int v = node0 + ty * 4 + i;
        if (v >= n) continue;
        float o[8];
#pragma unroll
        for (int jp = 0; jp < 4; jp++) {
            float2 e1 = unpk(a1[i][jp]);
            float2 e2 = unpk(a2[i][jp]);
            float x1 = e1.x + b1sh[j0 + 2 * jp];
            float x2 = e1.y + b1sh[j0 + 2 * jp + 1];
            float y1 = e2.x + b2sh[j0 + 2 * jp];
            float y2 = e2.y + b2sh[j0 + 2 * jp + 1];
            x1 = x1 > 0.f ? x1 : 0.01f * x1;
            x2 = x2 > 0.f ? x2 : 0.01f * x2;
            y1 = y1 > 0.f ? y1 : 0.01f * y1;
            y2 = y2 > 0.f ? y2 : 0.01f * y2;
            o[2 * jp]     = x1 + y1;
            o[2 * jp + 1] = x2 + y2;
        }
        float4 f4a = make_float4(o[0], o[1], o[2], o[3]);
        float4 f4b = make_float4(o[4], o[5], o[6], o[7]);
        hout[((size_t)v << 4) + (j0 >> 2)]     = f4a;
        hout[((size_t)v << 4) + (j0 >> 2) + 1] = f4b;
        *(float4*)(out + (size_t)v * 256 + out_off + j0)     = f4a;
        *(float4*)(out + (size_t)v * 256 + out_off + j0 + 4) = f4b;
    }
}

extern "C" void kernel_launch(void* const* d_in, const int* in_sizes, int n_in,
                              void* d_out, int out_size) {
    const float* x   = (const float*)d_in[0];
    const float* a   = (const float*)d_in[1];
    const float* W1s = (const float*)d_in[2];
    const float* b1s = (const float*)d_in[3];
    const float* W2s = (const float*)d_in[4];
    const float* b2s = (const float*)d_in[5];
    const int*   src = (const int*)d_in[6];
    const int*   dst = (const int*)d_in[7];
    float* out = (float*)d_out;

    int n  = in_sizes[0] / DIM;
    int ne = in_sizes[6];

    void* p;
    cudaGetSymbolAddress(&p, g_hbuf);  float4* hbuf = (float4*)p;
    cudaGetSymbolAddress(&p, g_off);   int*    off  = (int*)p;
    cudaGetSymbolAddress(&p, g_cur);   int*    cur  = (int*)p;
    cudaGetSymbolAddress(&p, g_edge);  int2*   edge = (int2*)p;

    const int SMEM = (128 * PAD * 2 + 4096 * 2 + 128) * 4;   // 102,912 B
    cudaFuncSetAttribute(layer_kernel, cudaFuncAttributeMaxDynamicSharedMemorySize, SMEM);

    // ---- CSR build (graph-only; reused by all 3 layers) ----
    zero_int_kernel<<<(n + 1023) / 1024, 1024>>>(cur, n);
    int hb = (ne / 4 + 255) / 256 + 1;
    hist_kernel<<<hb, 256>>>(dst, cur, ne);
    scan_kernel<<<1, 1024>>>(cur, off, cur, n);
    scatter_kernel<<<hb, 256>>>(src, dst, a, cur, edge, ne);

    // ---- 3 fused layers ----
    const float4* hin = (const float4*)x;
    int blocks = (n + 127) / 128;
    for (int l = 0; l < 3; l++) {
        float4* hout = hbuf + (size_t)(l & 1) * ((size_t)N_NODES * 16);
        layer_kernel<<<blocks, 256, SMEM>>>(
            hin, off, edge,
            (const float4*)(W1s + (size_t)l * 4096), b1s + l * 64,
            (const float4*)(W2s + (size_t)l * 4096), b2s + l * 64,
            hout, out, DIM * (l + 1), n, l == 0 ? 1 : 0);
        hin = hout;
    }
}

// round 4
// speedup vs baseline: 1.0957x; 1.0957x over previous
#include <cuda_runtime.h>
#include <cstdint>

#define N_NODES 100000
#define N_EDGES 3200000
#define DIM 64
#define PAD 68

// Scratch (device globals: no allocation allowed).
__device__ float4 g_hbuf[2][(size_t)N_NODES * 16];
__device__ float4 g_hn[(size_t)N_NODES * 16];
__device__ int    g_off[N_NODES + 1];
__device__ int    g_cur[N_NODES];
__device__ int2   g_edge[N_EDGES];   // (src, float_bits(a)) permuted by dst

// ---------------- CSR build ----------------

__global__ void zero_int_kernel(int* __restrict__ p, int n) {
    int i = blockIdx.x * blockDim.x + threadIdx.x;
    if (i < n) p[i] = 0;
}

__global__ void hist_kernel(const int* __restrict__ dst, int* __restrict__ cnt, int ne) {
    int e0 = (blockIdx.x * blockDim.x + threadIdx.x) * 8;
    if (e0 + 8 <= ne) {
        int4 d0 = *(const int4*)(dst + e0);
        int4 d1 = *(const int4*)(dst + e0 + 4);
        atomicAdd(&cnt[d0.x], 1); atomicAdd(&cnt[d0.y], 1);
        atomicAdd(&cnt[d0.z], 1); atomicAdd(&cnt[d0.w], 1);
        atomicAdd(&cnt[d1.x], 1); atomicAdd(&cnt[d1.y], 1);
        atomicAdd(&cnt[d1.z], 1); atomicAdd(&cnt[d1.w], 1);
    } else {
        for (int e = e0; e < ne; e++) atomicAdd(&cnt[__ldg(dst + e)], 1);
    }
}

// Single-block exclusive scan over cnt[0..n) -> off[0..n]; also cur[v] = off[v].
__global__ void scan_kernel(int* __restrict__ cnt, int* __restrict__ off,
                            int* __restrict__ cur, int n) {
    __shared__ int sh[1024];
    int t = threadIdx.x;
    int C = (n + 1023) >> 10;
    int base = t * C;
    int sum = 0;
    for (int i = 0; i < C; i++) {
        int idx = base + i;
        if (idx < n) sum += cnt[idx];
    }
    sh[t] = sum;
    __syncthreads();
    for (int d = 1; d < 1024; d <<= 1) {
        int tmp = (t >= d) ? sh[t - d] : 0;
        __syncthreads();
        sh[t] += tmp;
        __syncthreads();
    }
    int run = sh[t] - sum;
    for (int i = 0; i < C; i++) {
        int idx = base + i;
        if (idx < n) {
            int c = cnt[idx];
            off[idx] = run;
            cur[idx] = run;
            run += c;
        }
    }
    if (t == 1023) off[n] = sh[1023];
}

__global__ void scatter_kernel(const int* __restrict__ src, const int* __restrict__ dst,
                               const float* __restrict__ a,
                               int* __restrict__ cur, int2* __restrict__ edge, int ne) {
    int e0 = (blockIdx.x * blockDim.x + threadIdx.x) * 8;
    if (e0 + 8 <= ne) {
        int4   d0 = *(const int4*)(dst + e0);
        int4   d1 = *(const int4*)(dst + e0 + 4);
        int4   s0 = *(const int4*)(src + e0);
        int4   s1 = *(const int4*)(src + e0 + 4);
        float4 a0 = *(const float4*)(a + e0);
        float4 a1 = *(const float4*)(a + e0 + 4);
        int p0 = atomicAdd(&cur[d0.x], 1);
        int p1 = atomicAdd(&cur[d0.y], 1);
        int p2 = atomicAdd(&cur[d0.z], 1);
        int p3 = atomicAdd(&cur[d0.w], 1);
        int p4 = atomicAdd(&cur[d1.x], 1);
        int p5 = atomicAdd(&cur[d1.y], 1);
        int p6 = atomicAdd(&cur[d1.z], 1);
        int p7 = atomicAdd(&cur[d1.w], 1);
        edge[p0] = make_int2(s0.x, __float_as_int(a0.x));
        edge[p1] = make_int2(s0.y, __float_as_int(a0.y));
        edge[p2] = make_int2(s0.z, __float_as_int(a0.z));
        edge[p3] = make_int2(s0.w, __float_as_int(a0.w));
        edge[p4] = make_int2(s1.x, __float_as_int(a1.x));
        edge[p5] = make_int2(s1.y, __float_as_int(a1.y));
        edge[p6] = make_int2(s1.z, __float_as_int(a1.z));
        edge[p7] = make_int2(s1.w, __float_as_int(a1.w));
    } else {
        for (int e = e0; e < ne; e++) {
            int d = __ldg(dst + e);
            int pos = atomicAdd(&cur[d], 1);
            edge[pos] = make_int2(__ldg(src + e), __float_as_int(__ldg(a + e)));
        }
    }
}

// ---------------- Per-layer kernels ----------------

__global__ void copy_x_kernel(const float4* __restrict__ x, float4* __restrict__ out, int n16) {
    int i = blockIdx.x * blockDim.x + threadIdx.x;
    if (i >= n16) return;
    int v = i >> 4, c = i & 15;
    out[(size_t)v * 64 + c] = x[i];
}

// CSR gather-accumulate: h_n[v] = sum a_e * h[src_e]. 16 threads/node, 4-edge unroll.
__global__ void aggregate_csr(const float4* __restrict__ hin,
                              const int* __restrict__ off,
                              const int2* __restrict__ edge,
                              float4* __restrict__ hn, int n) {
    int g = blockIdx.x * blockDim.x + threadIdx.x;
    int v = g >> 4;
    if (v >= n) return;
    int c = g & 15;
    int i = __ldg(off + v), end = __ldg(off + v + 1);
    float4 acc0 = make_float4(0.f, 0.f, 0.f, 0.f);
    float4 acc1 = make_float4(0.f, 0.f, 0.f, 0.f);
    float4 acc2 = make_float4(0.f, 0.f, 0.f, 0.f);
    float4 acc3 = make_float4(0.f, 0.f, 0.f, 0.f);
    for (; i + 4 <= end; i += 4) {
        int2 e0 = __ldg(edge + i);
        int2 e1 = __ldg(edge + i + 1);
        int2 e2 = __ldg(edge + i + 2);
        int2 e3 = __ldg(edge + i + 3);
        float4 h0 = __ldg(hin + ((size_t)e0.x << 4) + c);
        float4 h1 = __ldg(hin + ((size_t)e1.x << 4) + c);
        float4 h2 = __ldg(hin + ((size_t)e2.x << 4) + c);
        float4 h3 = __ldg(hin + ((size_t)e3.x << 4) + c);
        float w0 = __int_as_float(e0.y), w1 = __int_as_float(e1.y);
        float w2 = __int_as_float(e2.y), w3 = __int_as_float(e3.y);
        acc0.x += w0 * h0.x; acc0.y += w0 * h0.y; acc0.z += w0 * h0.z; acc0.w += w0 * h0.w;
        acc1.x += w1 * h1.x; acc1.y += w1 * h1.y; acc1.z += w1 * h1.z; acc1.w += w1 * h1.w;
        acc2.x += w2 * h2.x; acc2.y += w2 * h2.y; acc2.z += w2 * h2.z; acc2.w += w2 * h2.w;
        acc3.x += w3 * h3.x; acc3.y += w3 * h3.y; acc3.z += w3 * h3.z; acc3.w += w3 * h3.w;
    }
    for (; i < end; i++) {
        int2 e0 = __ldg(edge + i);
        float4 h0 = __ldg(hin + ((size_t)e0.x << 4) + c);
        float w0 = __int_as_float(e0.y);
        acc0.x += w0 * h0.x; acc0.y += w0 * h0.y; acc0.z += w0 * h0.z; acc0.w += w0 * h0.w;
    }
    float4 r = make_float4((acc0.x + acc1.x) + (acc2.x + acc3.x),
                           (acc0.y + acc1.y) + (acc2.y + acc3.y),
                           (acc0.z + acc1.z) + (acc2.z + acc3.z),
                           (acc0.w + acc1.w) + (acc2.w + acc3.w));
    hn[((size_t)v << 4) + c] = r;
}

// ---------------- MLP: dual GEMM + activation, packed fma.rn.f32x2 ----------------

__device__ __forceinline__ void fma2(unsigned long long& acc,
                                     unsigned long long ab, unsigned long long bb) {
    asm("fma.rn.f32x2 %0, %1, %2, %0;" : "+l"(acc) : "l"(ab), "l"(bb));
}
__device__ __forceinline__ unsigned long long dup2(float s) {
    unsigned long long r;
    unsigned int u = __float_as_uint(s);
    asm("mov.b64 %0, {%1, %1};" : "=l"(r) : "r"(u));
    return r;
}
__device__ __forceinline__ float2 unpk(unsigned long long v) {
    unsigned int lo, hi;
    asm("mov.b64 {%0, %1}, %2;" : "=r"(lo), "=r"(hi) : "l"(v));
    return make_float2(__uint_as_float(lo), __uint_as_float(hi));
}

__global__ void __launch_bounds__(256, 2)
mlp_kernel(const float4* __restrict__ hin,
           const float4* __restrict__ hn,
           const float4* __restrict__ W1, const float* __restrict__ b1,
           const float4* __restrict__ W2, const float* __restrict__ b2,
           float4* __restrict__ hout, float* __restrict__ out,
           int out_off, int n) {
    extern __shared__ float sm[];
    float* Ssh  = sm;                  // [128][PAD]
    float* Psh  = Ssh + 128 * PAD;     // [128][PAD]
    float* W1sh = Psh + 128 * PAD;     // [64][64] [k][j]
    float* W2sh = W1sh + 4096;
    float* b1sh = W2sh + 4096;
    float* b2sh = b1sh + 64;

    int tid = threadIdx.x;
    int node0 = blockIdx.x << 7;

    for (int i = tid; i < 1024; i += 256) {
        ((float4*)W1sh)[i] = __ldg(W1 + i);
        ((float4*)W2sh)[i] = __ldg(W2 + i);
    }
    if (tid < 64) { b1sh[tid] = __ldg(b1 + tid); b2sh[tid] = __ldg(b2 + tid); }

    // Stage S = h + hn, P = h * hn   (128 nodes x 16 float4 = 2048 float4)
    for (int i = tid; i < 2048; i += 256) {
        int nl = i >> 4, c = i & 15;
        int v = node0 + nl;
        float4 hv = make_float4(0.f, 0.f, 0.f, 0.f);
        float4 nv = make_float4(0.f, 0.f, 0.f, 0.f);
        if (v < n) {
            hv = __ldg(hin + ((size_t)v << 4) + c);
            nv = __ldg(hn  + ((size_t)v << 4) + c);
        }
        float4 s4 = make_float4(hv.x + nv.x, hv.y + nv.y, hv.z + nv.z, hv.w + nv.w);
        float4 p4 = make_float4(hv.x * nv.x, hv.y * nv.y, hv.z * nv.z, hv.w * nv.w);
        *(float4*)(Ssh + nl * PAD + (c << 2)) = s4;
        *(float4*)(Psh + nl * PAD + (c << 2)) = p4;
    }
    __syncthreads();

    int tx = tid & 7;            // 8 output-dim groups of 8
    int ty = tid >> 3;           // 32 node groups of 4
    unsigned long long a1[4][4] = {};
    unsigned long long a2[4][4] = {};

#pragma unroll 4
    for (int k = 0; k < 64; k++) {
        const float* w1p = W1sh + (k << 6) + (tx << 3);
        const float* w2p = W2sh + (k << 6) + (tx << 3);
        ulonglong2 w1lo = *(const ulonglong2*)(w1p);
        ulonglong2 w1hi = *(const ulonglong2*)(w1p + 4);
        ulonglong2 w2lo = *(const ulonglong2*)(w2p);
        ulonglong2 w2hi = *(const ulonglong2*)(w2p + 4);
#pragma unroll
        for (int i = 0; i < 4; i++) {
            float s = Ssh[(ty * 4 + i) * PAD + k];
            float p = Psh[(ty * 4 + i) * PAD + k];
            unsigned long long ss = dup2(s), pp = dup2(p);
            fma2(a1[i][0], ss, w1lo.x);
            fma2(a1[i][1], ss, w1lo.y);
            fma2(a1[i][2], ss, w1hi.x);
            fma2(a1[i][3], ss, w1hi.y);
            fma2(a2[i][0], pp, w2lo.x);
            fma2(a2[i][1], pp, w2lo.y);
            fma2(a2[i][2], pp, w2hi.x);
            fma2(a2[i][3], pp, w2hi.y);
        }
    }

    int j0 = tx << 3;
#pragma unroll
    for (int i = 0; i < 4; i++) {
        int v = node0 + ty * 4 + i;
        if (v >= n) continue;
        float o[8];
#pragma unroll
        for (int jp = 0; jp < 4; jp++) {
            float2 e1 = unpk(a1[i][jp]);
            float2 e2 = unpk(a2[i][jp]);
            float x1 = e1.x + b1sh[j0 + 2 * jp];
            float x2 = e1.y + b1sh[j0 + 2 * jp + 1];
            float y1 = e2.x + b2sh[j0 + 2 * jp];
            float y2 = e2.y + b2sh[j0 + 2 * jp + 1];
            x1 = x1 > 0.f ? x1 : 0.01f * x1;
            x2 = x2 > 0.f ? x2 : 0.01f * x2;
            y1 = y1 > 0.f ? y1 : 0.01f * y1;
            y2 = y2 > 0.f ? y2 : 0.01f * y2;
            o[2 * jp]     = x1 + y1;
            o[2 * jp + 1] = x2 + y2;
        }
        float4 f4a = make_float4(o[0], o[1], o[2], o[3]);
        float4 f4b = make_float4(o[4], o[5], o[6], o[7]);
        hout[((size_t)v << 4) + (j0 >> 2)]     = f4a;
        hout[((size_t)v << 4) + (j0 >> 2) + 1] = f4b;
        *(float4*)(out + (size_t)v * 256 + out_off + j0)     = f4a;
        *(float4*)(out + (size_t)v * 256 + out_off + j0 + 4) = f4b;
    }
}

extern "C" void kernel_launch(void* const* d_in, const int* in_sizes, int n_in,
                              void* d_out, int out_size) {
    const float* x   = (const float*)d_in[0];
    const float* a   = (const float*)d_in[1];
    const float* W1s = (const float*)d_in[2];
    const float* b1s = (const float*)d_in[3];
    const float* W2s = (const float*)d_in[4];
    const float* b2s = (const float*)d_in[5];
    const int*   src = (const int*)d_in[6];
    const int*   dst = (const int*)d_in[7];
    float* out = (float*)d_out;

    int n   = in_sizes[0] / DIM;
    int ne  = in_sizes[6];
    int n16 = n * 16;

    void* p;
    cudaGetSymbolAddress(&p, g_hbuf);  float4* hbuf = (float4*)p;
    cudaGetSymbolAddress(&p, g_hn);    float4* hn   = (float4*)p;
    cudaGetSymbolAddress(&p, g_off);   int*    off  = (int*)p;
    cudaGetSymbolAddress(&p, g_cur);   int*    cur  = (int*)p;
    cudaGetSymbolAddress(&p, g_edge);  int2*   edge = (int2*)p;

    const int SMEM = (128 * PAD * 2 + 4096 * 2 + 128) * 4;   // 102,912 B
    cudaFuncSetAttribute(mlp_kernel, cudaFuncAttributeMaxDynamicSharedMemorySize, SMEM);

    // ---- CSR build (graph-only; reused by all 3 layers) ----
    zero_int_kernel<<<(n + 1023) / 1024, 1024>>>(cur, n);
    int hb = (ne / 8 + 255) / 256 + 1;
    hist_kernel<<<hb, 256>>>(dst, cur, ne);
    scan_kernel<<<1, 1024>>>(cur, off, cur, n);
    scatter_kernel<<<hb, 256>>>(src, dst, a, cur, edge, ne);

    copy_x_kernel<<<(n16 + 255) / 256, 256>>>((const float4*)x, (float4*)out, n16);

    const float4* hin = (const float4*)x;
    int mlp_blocks = (n + 127) / 128;
    for (int l = 0; l < 3; l++) {
        float4* hout = hbuf + (size_t)(l & 1) * ((size_t)N_NODES * 16);

        aggregate_csr<<<(n16 + 255) / 256, 256>>>(hin, off, edge, hn, n);

        mlp_kernel<<<mlp_blocks, 256, SMEM>>>(
            hin, hn,
            (const float4*)(W1s + (size_t)l * 4096), b1s + l * 64,
            (const float4*)(W2s + (size_t)l * 4096), b2s + l * 64,
            hout, out, DIM * (l + 1), n);

        hin = hout;
    }
}

// round 5
// speedup vs baseline: 1.2647x; 1.1542x over previous
#include <cuda_runtime.h>
#include <cstdint>

#define N_NODES 100000
#define N_EDGES 3200000
#define DIM 64

// Scratch (device globals: no allocation allowed).
__device__ float4 g_hbuf[2][(size_t)N_NODES * 16];
__device__ float4 g_hn[(size_t)N_NODES * 16];
__device__ int    g_off[N_NODES + 1];
__device__ int    g_cur[N_NODES];
__device__ int2   g_edge[N_EDGES];   // (src, float_bits(a)) permuted by dst

// ---------------- CSR build ----------------

__global__ void zero_int_kernel(int* __restrict__ p, int n) {
    int i = blockIdx.x * blockDim.x + threadIdx.x;
    if (i < n) p[i] = 0;
}

__global__ void hist_kernel(const int* __restrict__ dst, int* __restrict__ cnt, int ne) {
    int e0 = (blockIdx.x * blockDim.x + threadIdx.x) * 8;
    if (e0 + 8 <= ne) {
        int4 d0 = *(const int4*)(dst + e0);
        int4 d1 = *(const int4*)(dst + e0 + 4);
        atomicAdd(&cnt[d0.x], 1); atomicAdd(&cnt[d0.y], 1);
        atomicAdd(&cnt[d0.z], 1); atomicAdd(&cnt[d0.w], 1);
        atomicAdd(&cnt[d1.x], 1); atomicAdd(&cnt[d1.y], 1);
        atomicAdd(&cnt[d1.z], 1); atomicAdd(&cnt[d1.w], 1);
    } else {
        for (int e = e0; e < ne; e++) atomicAdd(&cnt[__ldg(dst + e)], 1);
    }
}

// Single-block exclusive scan over cnt[0..n) -> off[0..n]; also cur[v] = off[v].
__global__ void scan_kernel(int* __restrict__ cnt, int* __restrict__ off,
                            int* __restrict__ cur, int n) {
    __shared__ int sh[1024];
    int t = threadIdx.x;
    int C = (n + 1023) >> 10;
    int base = t * C;
    int sum = 0;
    for (int i = 0; i < C; i++) {
        int idx = base + i;
        if (idx < n) sum += cnt[idx];
    }
    sh[t] = sum;
    __syncthreads();
    for (int d = 1; d < 1024; d <<= 1) {
        int tmp = (t >= d) ? sh[t - d] : 0;
        __syncthreads();
        sh[t] += tmp;
        __syncthreads();
    }
    int run = sh[t] - sum;
    for (int i = 0; i < C; i++) {
        int idx = base + i;
        if (idx < n) {
            int c = cnt[idx];
            off[idx] = run;
            cur[idx] = run;
            run += c;
        }
    }
    if (t == 1023) off[n] = sh[1023];
}

__global__ void scatter_kernel(const int* __restrict__ src, const int* __restrict__ dst,
                               const float* __restrict__ a,
                               int* __restrict__ cur, int2* __restrict__ edge, int ne) {
    int e0 = (blockIdx.x * blockDim.x + threadIdx.x) * 8;
    if (e0 + 8 <= ne) {
        int4   d0 = *(const int4*)(dst + e0);
        int4   d1 = *(const int4*)(dst + e0 + 4);
        int4   s0 = *(const int4*)(src + e0);
        int4   s1 = *(const int4*)(src + e0 + 4);
        float4 a0 = *(const float4*)(a + e0);
        float4 a1 = *(const float4*)(a + e0 + 4);
        int p0 = atomicAdd(&cur[d0.x], 1);
        int p1 = atomicAdd(&cur[d0.y], 1);
        int p2 = atomicAdd(&cur[d0.z], 1);
        int p3 = atomicAdd(&cur[d0.w], 1);
        int p4 = atomicAdd(&cur[d1.x], 1);
        int p5 = atomicAdd(&cur[d1.y], 1);
        int p6 = atomicAdd(&cur[d1.z], 1);
        int p7 = atomicAdd(&cur[d1.w], 1);
        edge[p0] = make_int2(s0.x, __float_as_int(a0.x));
        edge[p1] = make_int2(s0.y, __float_as_int(a0.y));
        edge[p2] = make_int2(s0.z, __float_as_int(a0.z));
        edge[p3] = make_int2(s0.w, __float_as_int(a0.w));
        edge[p4] = make_int2(s1.x, __float_as_int(a1.x));
        edge[p5] = make_int2(s1.y, __float_as_int(a1.y));
        edge[p6] = make_int2(s1.z, __float_as_int(a1.z));
        edge[p7] = make_int2(s1.w, __float_as_int(a1.w));
    } else {
        for (int e = e0; e < ne; e++) {
            int d = __ldg(dst + e);
            int pos = atomicAdd(&cur[d], 1);
            edge[pos] = make_int2(__ldg(src + e), __float_as_int(__ldg(a + e)));
        }
    }
}

// ---------------- Per-layer kernels ----------------

__global__ void copy_x_kernel(const float4* __restrict__ x, float4* __restrict__ out, int n16) {
    int i = blockIdx.x * blockDim.x + threadIdx.x;
    if (i >= n16) return;
    int v = i >> 4, c = i & 15;
    out[(size_t)v * 64 + c] = x[i];
}

// CSR gather-accumulate (R2 form): 16 threads/node, 2-edge software pipeline.
__global__ void aggregate_csr(const float4* __restrict__ hin,
                              const int* __restrict__ off,
                              const int2* __restrict__ edge,
                              float4* __restrict__ hn, int n) {
    int g = blockIdx.x * blockDim.x + threadIdx.x;
    int v = g >> 4;
    if (v >= n) return;
    int c = g & 15;
    int i = __ldg(off + v), end = __ldg(off + v + 1);
    float4 acca = make_float4(0.f, 0.f, 0.f, 0.f);
    float4 accb = make_float4(0.f, 0.f, 0.f, 0.f);
    for (; i + 2 <= end; i += 2) {
        int2 ea = __ldg(edge + i);
        int2 eb = __ldg(edge + i + 1);
        float4 ha = __ldg(hin + ((size_t)ea.x << 4) + c);
        float4 hb = __ldg(hin + ((size_t)eb.x << 4) + c);
        float wa = __int_as_float(ea.y), wb = __int_as_float(eb.y);
        acca.x += wa * ha.x; acca.y += wa * ha.y;
        acca.z += wa * ha.z; acca.w += wa * ha.w;
        accb.x += wb * hb.x; accb.y += wb * hb.y;
        accb.z += wb * hb.z; accb.w += wb * hb.w;
    }
    if (i < end) {
        int2 ea = __ldg(edge + i);
        float4 ha = __ldg(hin + ((size_t)ea.x << 4) + c);
        float wa = __int_as_float(ea.y);
        acca.x += wa * ha.x; acca.y += wa * ha.y;
        acca.z += wa * ha.z; acca.w += wa * ha.w;
    }
    float4 r = make_float4(acca.x + accb.x, acca.y + accb.y,
                           acca.z + accb.z, acca.w + accb.w);
    hn[((size_t)v << 4) + c] = r;
}

// ---------------- MLP (R2 tiling, f32x2 inner loop) ----------------

__device__ __forceinline__ void fma2(unsigned long long& acc,
                                     unsigned long long ab, unsigned long long bb) {
    asm("fma.rn.f32x2 %0, %1, %2, %0;" : "+l"(acc) : "l"(ab), "l"(bb));
}
__device__ __forceinline__ unsigned long long dup2(float s) {
    unsigned long long r;
    unsigned int u = __float_as_uint(s);
    asm("mov.b64 %0, {%1, %1};" : "=l"(r) : "r"(u));
    return r;
}
__device__ __forceinline__ float2 unpk(unsigned long long v) {
    unsigned int lo, hi;
    asm("mov.b64 {%0, %1}, %2;" : "=r"(lo), "=r"(hi) : "l"(v));
    return make_float2(__uint_as_float(lo), __uint_as_float(hi));
}

// 64 nodes x 64 dims per block, 256 threads, 4x4 micro-tile (as 4x2 f32x2 pairs).
__global__ void mlp_kernel(const float4* __restrict__ hin,
                           const float4* __restrict__ hn,
                           const float4* __restrict__ W1,
                           const float*  __restrict__ b1,
                           const float4* __restrict__ W2,
                           const float*  __restrict__ b2,
                           float4* __restrict__ hout,
                           float*  __restrict__ out,
                           int out_off, int n) {
    extern __shared__ float sm[];
    float* Ssh  = sm;                // [64][68]
    float* Psh  = Ssh + 64 * 68;     // [64][68]
    float* W1sh = Psh + 64 * 68;     // [64][64] [k][j]
    float* W2sh = W1sh + 4096;
    float* b1sh = W2sh + 4096;
    float* b2sh = b1sh + 64;

    int tid = threadIdx.x;
    int node0 = blockIdx.x << 6;

    for (int i = tid; i < 1024; i += 256) {
        ((float4*)W1sh)[i] = __ldg(W1 + i);
        ((float4*)W2sh)[i] = __ldg(W2 + i);
    }
    if (tid < 64) { b1sh[tid] = __ldg(b1 + tid); b2sh[tid] = __ldg(b2 + tid); }

    for (int i = tid; i < 1024; i += 256) {
        int nl = i >> 4, c = i & 15;
        int v = node0 + nl;
        float4 hv = make_float4(0.f, 0.f, 0.f, 0.f);
        float4 nv = make_float4(0.f, 0.f, 0.f, 0.f);
        if (v < n) {
            hv = __ldg(hin + ((size_t)v << 4) + c);
            nv = __ldg(hn  + ((size_t)v << 4) + c);
        }
        float4 s4 = make_float4(hv.x + nv.x, hv.y + nv.y, hv.z + nv.z, hv.w + nv.w);
        float4 p4 = make_float4(hv.x * nv.x, hv.y * nv.y, hv.z * nv.z, hv.w * nv.w);
        *(float4*)(Ssh + nl * 68 + (c << 2)) = s4;
        *(float4*)(Psh + nl * 68 + (c << 2)) = p4;
    }
    __syncthreads();

    int tx = tid & 15, ty = tid >> 4;   // tx: 4-dim group, ty: 4-node group
    unsigned long long a1[4][2] = {};
    unsigned long long a2[4][2] = {};

#pragma unroll 8
    for (int k = 0; k < 64; k++) {
        ulonglong2 w1 = *(const ulonglong2*)(W1sh + (k << 6) + (tx << 2));
        ulonglong2 w2 = *(const ulonglong2*)(W2sh + (k << 6) + (tx << 2));
#pragma unroll
        for (int i = 0; i < 4; i++) {
            float s = Ssh[(ty * 4 + i) * 68 + k];
            float p = Psh[(ty * 4 + i) * 68 + k];
            unsigned long long ss = dup2(s), pp = dup2(p);
            fma2(a1[i][0], ss, w1.x);
            fma2(a1[i][1], ss, w1.y);
            fma2(a2[i][0], pp, w2.x);
            fma2(a2[i][1], pp, w2.y);
        }
    }

    int j0 = tx << 2;
#pragma unroll
    for (int i = 0; i < 4; i++) {
        int v = node0 + ty * 4 + i;
        if (v >= n) continue;
        float o[4];
#pragma unroll
        for (int jp = 0; jp < 2; jp++) {
            float2 e1 = unpk(a1[i][jp]);
            float2 e2 = unpk(a2[i][jp]);
            float x1 = e1.x + b1sh[j0 + 2 * jp];
            float x2 = e1.y + b1sh[j0 + 2 * jp + 1];
            float y1 = e2.x + b2sh[j0 + 2 * jp];
            float y2 = e2.y + b2sh[j0 + 2 * jp + 1];
            x1 = x1 > 0.f ? x1 : 0.01f * x1;
            x2 = x2 > 0.f ? x2 : 0.01f * x2;
            y1 = y1 > 0.f ? y1 : 0.01f * y1;
            y2 = y2 > 0.f ? y2 : 0.01f * y2;
            o[2 * jp]     = x1 + y1;
            o[2 * jp + 1] = x2 + y2;
        }
        float4 f4 = make_float4(o[0], o[1], o[2], o[3]);
        hout[((size_t)v << 4) + tx] = f4;
        *(float4*)(out + (size_t)v * 256 + out_off + j0) = f4;
    }
}

extern "C" void kernel_launch(void* const* d_in, const int* in_sizes, int n_in,
                              void* d_out, int out_size) {
    const float* x   = (const float*)d_in[0];
    const float* a   = (const float*)d_in[1];
    const float* W1s = (const float*)d_in[2];
    const float* b1s = (const float*)d_in[3];
    const float* W2s = (const float*)d_in[4];
    const float* b2s = (const float*)d_in[5];
    const int*   src = (const int*)d_in[6];
    const int*   dst = (const int*)d_in[7];
    float* out = (float*)d_out;

    int n   = in_sizes[0] / DIM;
    int ne  = in_sizes[6];
    int n16 = n * 16;

    void* p;
    cudaGetSymbolAddress(&p, g_hbuf);  float4* hbuf = (float4*)p;
    cudaGetSymbolAddress(&p, g_hn);    float4* hn   = (float4*)p;
    cudaGetSymbolAddress(&p, g_off);   int*    off  = (int*)p;
    cudaGetSymbolAddress(&p, g_cur);   int*    cur  = (int*)p;
    cudaGetSymbolAddress(&p, g_edge);  int2*   edge = (int2*)p;

    const int SMEM = (64 * 68 * 2 + 4096 * 2 + 128) * 4;  // 68096 B
    cudaFuncSetAttribute(mlp_kernel, cudaFuncAttributeMaxDynamicSharedMemorySize, SMEM);

    // ---- CSR build (graph-only; reused by all 3 layers) ----
    zero_int_kernel<<<(n + 1023) / 1024, 1024>>>(cur, n);
    int hb = (ne / 8 + 255) / 256 + 1;
    hist_kernel<<<hb, 256>>>(dst, cur, ne);
    scan_kernel<<<1, 1024>>>(cur, off, cur, n);
    scatter_kernel<<<hb, 256>>>(src, dst, a, cur, edge, ne);

    copy_x_kernel<<<(n16 + 255) / 256, 256>>>((const float4*)x, (float4*)out, n16);

    const float4* hin = (const float4*)x;
    int mlp_blocks = (n + 63) / 64;
    for (int l = 0; l < 3; l++) {
        float4* hout = hbuf + (size_t)(l & 1) * ((size_t)N_NODES * 16);

        aggregate_csr<<<(n16 + 255) / 256, 256>>>(hin, off, edge, hn, n);

        mlp_kernel<<<mlp_blocks, 256, SMEM>>>(
            hin, hn,
            (const float4*)(W1s + (size_t)l * 4096), b1s + l * 64,
            (const float4*)(W2s + (size_t)l * 4096), b2s + l * 64,
            hout, out, DIM * (l + 1), n);

        hin = hout;
    }
}

// round 6
// speedup vs baseline: 1.6262x; 1.2859x over previous
#include <cuda_runtime.h>
#include <cstdint>

#define N_NODES 100000
#define N_EDGES 3200000
#define DIM 64
#define CAP 128          // per-node bucket capacity; P(deg>=128), deg~Poisson(32), ~e^-81
#define CAP_SHIFT 7

// Scratch (device globals: no allocation allowed).
__device__ float4 g_hbuf[2][(size_t)N_NODES * 16];
__device__ float4 g_hn[(size_t)N_NODES * 16];
__device__ int    g_cnt[N_NODES];
__device__ int2   g_edge[(size_t)N_NODES * CAP];   // bucketed (src, float_bits(a))

// ---------------- Bucketed edge build (single pass, no scan) ----------------

__global__ void zero_int_kernel(int* __restrict__ p, int n) {
    int i = blockIdx.x * blockDim.x + threadIdx.x;
    if (i < n) p[i] = 0;
}

__global__ void scatter_kernel(const int* __restrict__ src, const int* __restrict__ dst,
                               const float* __restrict__ a,
                               int* __restrict__ cnt, int2* __restrict__ edge, int ne) {
    int e0 = (blockIdx.x * blockDim.x + threadIdx.x) * 8;
    if (e0 + 8 <= ne) {
        int4   d0 = *(const int4*)(dst + e0);
        int4   d1 = *(const int4*)(dst + e0 + 4);
        int4   s0 = *(const int4*)(src + e0);
        int4   s1 = *(const int4*)(src + e0 + 4);
        float4 a0 = *(const float4*)(a + e0);
        float4 a1 = *(const float4*)(a + e0 + 4);
        int p0 = atomicAdd(&cnt[d0.x], 1);
        int p1 = atomicAdd(&cnt[d0.y], 1);
        int p2 = atomicAdd(&cnt[d0.z], 1);
        int p3 = atomicAdd(&cnt[d0.w], 1);
        int p4 = atomicAdd(&cnt[d1.x], 1);
        int p5 = atomicAdd(&cnt[d1.y], 1);
        int p6 = atomicAdd(&cnt[d1.z], 1);
        int p7 = atomicAdd(&cnt[d1.w], 1);
        edge[((size_t)d0.x << CAP_SHIFT) + p0] = make_int2(s0.x, __float_as_int(a0.x));
        edge[((size_t)d0.y << CAP_SHIFT) + p1] = make_int2(s0.y, __float_as_int(a0.y));
        edge[((size_t)d0.z << CAP_SHIFT) + p2] = make_int2(s0.z, __float_as_int(a0.z));
        edge[((size_t)d0.w << CAP_SHIFT) + p3] = make_int2(s0.w, __float_as_int(a0.w));
        edge[((size_t)d1.x << CAP_SHIFT) + p4] = make_int2(s1.x, __float_as_int(a1.x));
        edge[((size_t)d1.y << CAP_SHIFT) + p5] = make_int2(s1.y, __float_as_int(a1.y));
        edge[((size_t)d1.z << CAP_SHIFT) + p6] = make_int2(s1.z, __float_as_int(a1.z));
        edge[((size_t)d1.w << CAP_SHIFT) + p7] = make_int2(s1.w, __float_as_int(a1.w));
    } else {
        for (int e = e0; e < ne; e++) {
            int d = __ldg(dst + e);
            int pos = atomicAdd(&cnt[d], 1);
            edge[((size_t)d << CAP_SHIFT) + pos] =
                make_int2(__ldg(src + e), __float_as_int(__ldg(a + e)));
        }
    }
}

// ---------------- Aggregate: h_n[v] = sum a_e * h[src_e] ----------------
// 16 threads/node, 2-edge software pipeline (measured-best form).

__global__ void aggregate_csr(const float4* __restrict__ hin,
                              const int* __restrict__ cnt,
                              const int2* __restrict__ edge,
                              float4* __restrict__ hn, int n) {
    int g = blockIdx.x * blockDim.x + threadIdx.x;
    int v = g >> 4;
    if (v >= n) return;
    int c = g & 15;
    size_t base = (size_t)v << CAP_SHIFT;
    int i = 0, end = __ldg(cnt + v);
    float4 acca = make_float4(0.f, 0.f, 0.f, 0.f);
    float4 accb = make_float4(0.f, 0.f, 0.f, 0.f);
    for (; i + 2 <= end; i += 2) {
        int2 ea = __ldg(edge + base + i);
        int2 eb = __ldg(edge + base + i + 1);
        float4 ha = __ldg(hin + ((size_t)ea.x << 4) + c);
        float4 hb = __ldg(hin + ((size_t)eb.x << 4) + c);
        float wa = __int_as_float(ea.y), wb = __int_as_float(eb.y);
        acca.x += wa * ha.x; acca.y += wa * ha.y;
        acca.z += wa * ha.z; acca.w += wa * ha.w;
        accb.x += wb * hb.x; accb.y += wb * hb.y;
        accb.z += wb * hb.z; accb.w += wb * hb.w;
    }
    if (i < end) {
        int2 ea = __ldg(edge + base + i);
        float4 ha = __ldg(hin + ((size_t)ea.x << 4) + c);
        float wa = __int_as_float(ea.y);
        acca.x += wa * ha.x; acca.y += wa * ha.y;
        acca.z += wa * ha.z; acca.w += wa * ha.w;
    }
    float4 r = make_float4(acca.x + accb.x, acca.y + accb.y,
                           acca.z + accb.z, acca.w + accb.w);
    hn[((size_t)v << 4) + c] = r;
}

// ---------------- MLP (R2 tiling, f32x2 inner loop, occ=3) ----------------

__device__ __forceinline__ void fma2(unsigned long long& acc,
                                     unsigned long long ab, unsigned long long bb) {
    asm("fma.rn.f32x2 %0, %1, %2, %0;" : "+l"(acc) : "l"(ab), "l"(bb));
}
__device__ __forceinline__ unsigned long long dup2(float s) {
    unsigned long long r;
    unsigned int u = __float_as_uint(s);
    asm("mov.b64 %0, {%1, %1};" : "=l"(r) : "r"(u));
    return r;
}
__device__ __forceinline__ float2 unpk(unsigned long long v) {
    unsigned int lo, hi;
    asm("mov.b64 {%0, %1}, %2;" : "=r"(lo), "=r"(hi) : "l"(v));
    return make_float2(__uint_as_float(lo), __uint_as_float(hi));
}

// 64 nodes x 64 dims per block, 256 threads, 4-node x 4-dim micro-tile (4x2 f32x2).
__global__ void __launch_bounds__(256, 3)
mlp_kernel(const float4* __restrict__ hin,
           const float4* __restrict__ hn,
           const float4* __restrict__ W1,
           const float*  __restrict__ b1,
           const float4* __restrict__ W2,
           const float*  __restrict__ b2,
           float4* __restrict__ hout,
           float*  __restrict__ out,
           int out_off, int n, int write_x) {
    extern __shared__ float sm[];
    float* Ssh  = sm;                // [64][68]
    float* Psh  = Ssh + 64 * 68;     // [64][68]
    float* W1sh = Psh + 64 * 68;     // [64][64] [k][j]
    float* W2sh = W1sh + 4096;
    float* b1sh = W2sh + 4096;
    float* b2sh = b1sh + 64;

    int tid = threadIdx.x;
    int node0 = blockIdx.x << 6;

    for (int i = tid; i < 1024; i += 256) {
        ((float4*)W1sh)[i] = __ldg(W1 + i);
        ((float4*)W2sh)[i] = __ldg(W2 + i);
    }
    if (tid < 64) { b1sh[tid] = __ldg(b1 + tid); b2sh[tid] = __ldg(b2 + tid); }

    for (int i = tid; i < 1024; i += 256) {
        int nl = i >> 4, c = i & 15;
        int v = node0 + nl;
        float4 hv = make_float4(0.f, 0.f, 0.f, 0.f);
        float4 nv = make_float4(0.f, 0.f, 0.f, 0.f);
        if (v < n) {
            hv = __ldg(hin + ((size_t)v << 4) + c);
            nv = __ldg(hn  + ((size_t)v << 4) + c);
            if (write_x) *(float4*)(out + (size_t)v * 256 + (c << 2)) = hv;
        }
        float4 s4 = make_float4(hv.x + nv.x, hv.y + nv.y, hv.z + nv.z, hv.w + nv.w);
        float4 p4 = make_float4(hv.x * nv.x, hv.y * nv.y, hv.z * nv.z, hv.w * nv.w);
        *(float4*)(Ssh + nl * 68 + (c << 2)) = s4;
        *(float4*)(Psh + nl * 68 + (c << 2)) = p4;
    }
    __syncthreads();

    int tx = tid & 15, ty = tid >> 4;   // tx: 4-dim group, ty: 4-node group
    unsigned long long a1[4][2] = {};
    unsigned long long a2[4][2] = {};

#pragma unroll 8
    for (int k = 0; k < 64; k++) {
        ulonglong2 w1 = *(const ulonglong2*)(W1sh + (k << 6) + (tx << 2));
        ulonglong2 w2 = *(const ulonglong2*)(W2sh + (k << 6) + (tx << 2));
#pragma unroll
        for (int i = 0; i < 4; i++) {
            float s = Ssh[(ty * 4 + i) * 68 + k];
            float p = Psh[(ty * 4 + i) * 68 + k];
            unsigned long long ss = dup2(s), pp = dup2(p);
            fma2(a1[i][0], ss, w1.x);
            fma2(a1[i][1], ss, w1.y);
            fma2(a2[i][0], pp, w2.x);
            fma2(a2[i][1], pp, w2.y);
        }
    }

    int j0 = tx << 2;
#pragma unroll
    for (int i = 0; i < 4; i++) {
        int v = node0 + ty * 4 + i;
        if (v >= n) continue;
        float o[4];
#pragma unroll
        for (int jp = 0; jp < 2; jp++) {
            float2 e1 = unpk(a1[i][jp]);
            float2 e2 = unpk(a2[i][jp]);
            float x1 = e1.x + b1sh[j0 + 2 * jp];
            float x2 = e1.y + b1sh[j0 + 2 * jp + 1];
            float y1 = e2.x + b2sh[j0 + 2 * jp];
            float y2 = e2.y + b2sh[j0 + 2 * jp + 1];
            x1 = x1 > 0.f ? x1 : 0.01f * x1;
            x2 = x2 > 0.f ? x2 : 0.01f * x2;
            y1 = y1 > 0.f ? y1 : 0.01f * y1;
            y2 = y2 > 0.f ? y2 : 0.01f * y2;
            o[2 * jp]     = x1 + y1;
            o[2 * jp + 1] = x2 + y2;
        }
        float4 f4 = make_float4(o[0], o[1], o[2], o[3]);
        hout[((size_t)v << 4) + tx] = f4;
        *(float4*)(out + (size_t)v * 256 + out_off + j0) = f4;
    }
}

extern "C" void kernel_launch(void* const* d_in, const int* in_sizes, int n_in,
                              void* d_out, int out_size) {
    const float* x   = (const float*)d_in[0];
    const float* a   = (const float*)d_in[1];
    const float* W1s = (const float*)d_in[2];
    const float* b1s = (const float*)d_in[3];
    const float* W2s = (const float*)d_in[4];
    const float* b2s = (const float*)d_in[5];
    const int*   src = (const int*)d_in[6];
    const int*   dst = (const int*)d_in[7];
    float* out = (float*)d_out;

    int n   = in_sizes[0] / DIM;
    int ne  = in_sizes[6];
    int n16 = n * 16;

    void* p;
    cudaGetSymbolAddress(&p, g_hbuf);  float4* hbuf = (float4*)p;
    cudaGetSymbolAddress(&p, g_hn);    float4* hn   = (float4*)p;
    cudaGetSymbolAddress(&p, g_cnt);   int*    cnt  = (int*)p;
    cudaGetSymbolAddress(&p, g_edge);  int2*   edge = (int2*)p;

    const int SMEM = (64 * 68 * 2 + 4096 * 2 + 128) * 4;  // 68096 B
    cudaFuncSetAttribute(mlp_kernel, cudaFuncAttributeMaxDynamicSharedMemorySize, SMEM);

    // ---- Bucketed edge build: one zero + one scatter pass ----
    zero_int_kernel<<<(n + 1023) / 1024, 1024>>>(cnt, n);
    int sb = (ne / 8 + 255) / 256 + 1;
    scatter_kernel<<<sb, 256>>>(src, dst, a, cnt, edge, ne);

    const float4* hin = (const float4*)x;
    int mlp_blocks = (n + 63) / 64;
    for (int l = 0; l < 3; l++) {
        float4* hout = hbuf + (size_t)(l & 1) * ((size_t)N_NODES * 16);

        aggregate_csr<<<(n16 + 255) / 256, 256>>>(hin, cnt, edge, hn, n);

        mlp_kernel<<<mlp_blocks, 256, SMEM>>>(
            hin, hn,
            (const float4*)(W1s + (size_t)l * 4096), b1s + l * 64,
            (const float4*)(W2s + (size_t)l * 4096), b2s + l * 64,
            hout, out, DIM * (l + 1), n, l == 0 ? 1 : 0);

        hin = hout;
    }
}